// round 14
// baseline (speedup 1.0000x reference)
#include <cuda_runtime.h>
#include <cuda_fp16.h>
#include <cstdint>

// Problem constants
#define NB      16
#define CDIM    64
#define HWDIM   4096
#define NTOT    65536
#define KCB     512
#define OUT_Q   4194304
#define OFF_LOSS (OUT_Q)
#define OFF_PERP (OUT_Q + 1)
#define OFF_ACT  (OUT_Q + 2)
#define OFF_IDX  (OUT_Q + 3)

#define TPB     512
#define GRID    148
#define TILEP   64
#define NTILES  (NTOT / TILEP)      // 1024 -> 6.92/CTA -> 0.988 balance

// smem rows padded to 72 halves (144B = 36 banks) -> ldmatrix conflict-free
#define ROWB    144
// ---- dynamic smem byte offsets ----
// Transient (used once for A-fragment load, then dead):
#define SO_EH    0                  // E_hi fp16 [512][72h] = 73728
#define SO_EL    73728              // E_lo fp16            = 73728
// Persistent:
#define SO_SNORM 147456             // 512 f                = 2048
#define SO_XH    149504             // X_hi fp16 [64][72h]  = 9216
#define SO_XF    158720             // X fp32 [64][68]      = 17408
#define SO_CM    176128             // cand m [64][16][2] f = 8192
#define SO_CK    184320             // cand k [64][16][2] i = 8192
#define SO_HIST  192512             // 512 u32
#define SO_SBK   194560             // 64 int
#define SO_WSUM  194816             // 16 f
#define SO_RD    194880             // float [3][64] = 768
#define SO_RK    195648             // int   [3][64] = 768
#define SMEM_BYTES 196416

__device__ float        g_loss;
__device__ unsigned int g_hist[KCB];
__device__ unsigned int g_count;

// ---------------- family-portable tensor helpers (sm_80+ PTX only) --------
__device__ __forceinline__ void mma_f16(float* d, const uint32_t* a,
                                        const uint32_t* b) {
    asm volatile(
        "mma.sync.aligned.m16n8k16.row.col.f32.f16.f16.f32 "
        "{%0,%1,%2,%3}, {%4,%5,%6,%7}, {%8,%9}, {%0,%1,%2,%3};"
        : "+f"(d[0]), "+f"(d[1]), "+f"(d[2]), "+f"(d[3])
        : "r"(a[0]), "r"(a[1]), "r"(a[2]), "r"(a[3]), "r"(b[0]), "r"(b[1]));
}
__device__ __forceinline__ void ldsm4(uint32_t* r, uint32_t addr) {
    asm volatile("ldmatrix.sync.aligned.m8n8.x4.shared.b16 {%0,%1,%2,%3}, [%4];"
                 : "=r"(r[0]), "=r"(r[1]), "=r"(r[2]), "=r"(r[3]) : "r"(addr));
}
__device__ __forceinline__ uint32_t pack_h2(float f0, float f1) {
    __half h0 = __float2half_rn(f0);
    __half h1 = __float2half_rn(f1);
    return (uint32_t)__half_as_ushort(h0) | ((uint32_t)__half_as_ushort(h1) << 16);
}
__device__ __forceinline__ void pack_hilo_f16(float f0, float f1,
                                              uint32_t& whi, uint32_t& wlo) {
    __half h0 = __float2half_rn(f0);
    __half h1 = __float2half_rn(f1);
    float r0 = f0 - __half2float(h0);
    float r1 = f1 - __half2float(h1);
    __half l0 = __float2half_rn(r0);
    __half l1 = __float2half_rn(r1);
    whi = (uint32_t)__half_as_ushort(h0) | ((uint32_t)__half_as_ushort(h1) << 16);
    wlo = (uint32_t)__half_as_ushort(l0) | ((uint32_t)__half_as_ushort(l1) << 16);
}
__device__ __forceinline__ void top2_upd(float m, int k,
                                         float& b1, float& b2, int& k1, int& k2) {
    if (m > b2) {
        if (m > b1) { b2 = b1; k2 = k1; b1 = m; k1 = k; }
        else        { b2 = m;  k2 = k; }
    }
}
__device__ __forceinline__ void top3_upd(float m, int k,
                                         float& b1, float& b2, float& b3,
                                         int& k1, int& k2, int& k3) {
    if (m > b3) {
        if (m > b2) {
            b3 = b2; k3 = k2;
            if (m > b1) { b2 = b1; k2 = k1; b1 = m; k1 = k; }
            else        { b2 = m;  k2 = k; }
        } else { b3 = m; k3 = k; }
    }
}

// ---------------------------------------------------------------------------
extern __shared__ char sm[];

__global__ __launch_bounds__(TPB, 1)
void vq_main(const float* __restrict__ x,
             const float* __restrict__ E,
             const float* __restrict__ w,
             float* __restrict__ out) {
    float*        snorm = (float*)(sm + SO_SNORM);
    float*        sxf   = (float*)(sm + SO_XF);
    float*        cm    = (float*)(sm + SO_CM);
    int*          ck    = (int*)(sm + SO_CK);
    unsigned int* shist = (unsigned int*)(sm + SO_HIST);
    int*          sbk   = (int*)(sm + SO_SBK);
    float*        wsum  = (float*)(sm + SO_WSUM);
    float*        rd    = (float*)(sm + SO_RD);
    int*          rk    = (int*)(sm + SO_RK);
    __shared__ unsigned int s_rank;

    const int tid  = threadIdx.x;
    const int wid  = tid >> 5;
    const int lane = tid & 31;

    // ---- one-time: codebook -> fp16 hi/lo (transient smem) + norms
    {
        const int k = tid;
        const float4* er = reinterpret_cast<const float4*>(E + (k << 6));
        char* bh = sm + SO_EH + k * ROWB;
        char* bl = sm + SO_EL + k * ROWB;
        float s = 0.f;
#pragma unroll
        for (int i = 0; i < 16; i++) {
            float4 v = er[i];
            s = fmaf(v.x, v.x, s); s = fmaf(v.y, v.y, s);
            s = fmaf(v.z, v.z, s); s = fmaf(v.w, v.w, s);
            uint32_t whi, wlo;
            pack_hilo_f16(v.x, v.y, whi, wlo);
            *(uint32_t*)(bh + i * 8)     = whi;
            *(uint32_t*)(bl + i * 8)     = wlo;
            pack_hilo_f16(v.z, v.w, whi, wlo);
            *(uint32_t*)(bh + i * 8 + 4) = whi;
            *(uint32_t*)(bl + i * 8 + 4) = wlo;
        }
        snorm[k] = s;
        shist[k] = 0u;
    }
    __syncthreads();

    const uint32_t smu = (uint32_t)__cvta_generic_to_shared(sm);
    const int sel = lane >> 3;

    // ---- one-time: load this warp's 32 codes as persistent A fragments
    //      (fp16 hi + lo), then the E fp16 smem region is dead.
    uint32_t eh[32], el[32];
    {
        const int mrow0 = (wid << 5) + (lane & 7) + ((sel & 1) << 3);
        const uint32_t acol = (uint32_t)((sel >> 1) << 4);
#pragma unroll
        for (int m = 0; m < 2; m++) {
            const uint32_t abase = (uint32_t)((mrow0 + (m << 4)) * ROWB) + acol;
#pragma unroll
            for (int kt = 0; kt < 4; kt++) {
                ldsm4(eh + (m << 4) + (kt << 2), smu + SO_EH + abase + kt * 32);
                ldsm4(el + (m << 4) + (kt << 2), smu + SO_EL + abase + kt * 32);
            }
        }
    }
    // per-lane code ids + folded -||e||^2/2 accumulator inits
    const int cA0 = (wid << 5) + (lane >> 2);
    const int cA1 = cA0 + 8;
    const int cB0 = cA0 + 16;
    const int cB1 = cA0 + 24;
    const float hA0 = -0.5f * snorm[cA0];
    const float hA1 = -0.5f * snorm[cA1];
    const float hB0 = -0.5f * snorm[cB0];
    const float hB1 = -0.5f * snorm[cB1];

    const int pw  = tid & 63;     // staging point
    const int cgi = tid >> 6;     // staging channel group (0..7)

    // X-as-B ldmatrix lane addressing
    const uint32_t bln = (uint32_t)((lane & 7) * ROWB + (lane >> 3) * 16);
    const uint32_t bB  = smu + SO_XH + bln;

    float loss_acc = 0.f, xsq_acc = 0.f;

    for (int t = blockIdx.x; t < NTILES; t += GRID) {
        const int nb  = t << 6;
        const int b   = nb >> 12;
        const int hwb = nb & (HWDIM - 1);
        const float* xg = x + (size_t)b * CDIM * HWDIM + hwb;

        // ---- stage X tile: fp16 hi (MMA B) + fp32 (rescore)
#pragma unroll
        for (int jj = 0; jj < 4; jj++) {
            int c0 = (cgi << 3) + (jj << 1);
            float v0 = xg[(size_t)c0 * HWDIM + pw];
            float v1 = xg[(size_t)(c0 + 1) * HWDIM + pw];
            xsq_acc = fmaf(v0, v0, xsq_acc);
            xsq_acc = fmaf(v1, v1, xsq_acc);
            *(uint32_t*)(sm + SO_XH + pw * ROWB + c0 * 2) = pack_h2(v0, v1);
            sxf[pw * 68 + c0]     = v0;
            sxf[pw * 68 + c0 + 1] = v1;
        }
        __syncthreads();

        // ---- scan: 8 n-tiles of 8 points; D[code, point] via 2 fp16 products
#pragma unroll
        for (int nt = 0; nt < 8; nt++) {
            const uint32_t nbyt = (uint32_t)(nt * 8) * ROWB;
            uint32_t bx[8];
            ldsm4(bx,     bB + nbyt);         // k 0..31
            ldsm4(bx + 4, bB + nbyt + 64);    // k 32..63

            float acc1[4] = {hA0, hA0, hA1, hA1};   // Mtile0, eh product
            float acc2[4] = {0.f, 0.f, 0.f, 0.f};   // Mtile0, el product
            float acc3[4] = {hB0, hB0, hB1, hB1};   // Mtile1, eh
            float acc4[4] = {0.f, 0.f, 0.f, 0.f};   // Mtile1, el
#pragma unroll
            for (int kt = 0; kt < 4; kt++) {
                mma_f16(acc1, eh + (kt << 2),      bx + (kt << 1));
                mma_f16(acc2, el + (kt << 2),      bx + (kt << 1));
                mma_f16(acc3, eh + 16 + (kt << 2), bx + (kt << 1));
                mma_f16(acc4, el + 16 + (kt << 2), bx + (kt << 1));
            }
            // lane holds codes {cA0,cA1,cB0,cB1} x points {p0, p0+1}
            // acc[0],[1]: rows r (cA0/cB0) cols p0,p0+1 ; acc[2],[3]: rows +8
            float b1 = -3.4e38f, b2 = -3.4e38f;      // point p0
            float d1 = -3.4e38f, d2 = -3.4e38f;      // point p1
            int   kb1 = 0, kb2 = 0, kd1 = 0, kd2 = 0;
            top2_upd(acc1[0] + acc2[0], cA0, b1, b2, kb1, kb2);
            top2_upd(acc1[2] + acc2[2], cA1, b1, b2, kb1, kb2);
            top2_upd(acc3[0] + acc4[0], cB0, b1, b2, kb1, kb2);
            top2_upd(acc3[2] + acc4[2], cB1, b1, b2, kb1, kb2);
            top2_upd(acc1[1] + acc2[1], cA0, d1, d2, kd1, kd2);
            top2_upd(acc1[3] + acc2[3], cA1, d1, d2, kd1, kd2);
            top2_upd(acc3[1] + acc4[1], cB0, d1, d2, kd1, kd2);
            top2_upd(acc3[3] + acc4[3], cB1, d1, d2, kd1, kd2);

            // merge across the 8 lanes sharing each point (bfly 4, 8, 16)
#pragma unroll
            for (int off = 4; off <= 16; off <<= 1) {
                float o1 = __shfl_xor_sync(0xFFFFFFFFu, b1, off);
                float o2 = __shfl_xor_sync(0xFFFFFFFFu, b2, off);
                int   q1 = __shfl_xor_sync(0xFFFFFFFFu, kb1, off);
                int   q2 = __shfl_xor_sync(0xFFFFFFFFu, kb2, off);
                top2_upd(o1, q1, b1, b2, kb1, kb2);
                top2_upd(o2, q2, b1, b2, kb1, kb2);
                o1 = __shfl_xor_sync(0xFFFFFFFFu, d1, off);
                o2 = __shfl_xor_sync(0xFFFFFFFFu, d2, off);
                q1 = __shfl_xor_sync(0xFFFFFFFFu, kd1, off);
                q2 = __shfl_xor_sync(0xFFFFFFFFu, kd2, off);
                top2_upd(o1, q1, d1, d2, kd1, kd2);
                top2_upd(o2, q2, d1, d2, kd1, kd2);
            }
            if ((lane >> 2) == 0) {
                const int p0 = (nt << 3) + ((lane & 3) << 1);
                int base0 = (p0 << 5) + (wid << 1);
                int base1 = base0 + 32;
                cm[base0] = b1; cm[base0 + 1] = b2;
                ck[base0] = kb1; ck[base0 + 1] = kb2;
                cm[base1] = d1; cm[base1 + 1] = d2;
                ck[base1] = kd1; ck[base1 + 1] = kd2;
            }
        }
        __syncthreads();

        // ---- distributed exact rescore: thread (p, r), r = tid>>6 < 3.
        //      Redundant deterministic top-3 over 32 candidates; EXACT fp32
        //      distance in R1 formula/order.
        if (tid < 192) {
            const int p = tid & 63;
            const int r = tid >> 6;
            float m1 = -3.4e38f, m2 = -3.4e38f, m3 = -3.4e38f;
            int   i1 = 0, i2 = 0, i3 = 0;
#pragma unroll
            for (int ww = 0; ww < 16; ww++) {
                int bidx = (p << 5) + (ww << 1);
                top3_upd(cm[bidx],     ck[bidx],     m1, m2, m3, i1, i2, i3);
                top3_upd(cm[bidx + 1], ck[bidx + 1], m1, m2, m3, i1, i2, i3);
            }
            const int k = (r == 0) ? i1 : (r == 1) ? i2 : i3;
            const float4* xr4 = reinterpret_cast<const float4*>(sxf + p * 68);
            const float4* er  = reinterpret_cast<const float4*>(E + (k << 6));
            float q0 = 0.f, q1 = 0.f, q2 = 0.f, q3 = 0.f;
#pragma unroll
            for (int i = 0; i < 16; i++) {
                float4 xv = xr4[i];
                float4 ev = er[i];
                q0 = fmaf(xv.x, ev.x, q0);
                q1 = fmaf(xv.y, ev.y, q1);
                q2 = fmaf(xv.z, ev.z, q2);
                q3 = fmaf(xv.w, ev.w, q3);
            }
            float dot = (q0 + q1) + (q2 + q3);
            rd[(r << 6) + p] = fmaf(-2.f, dot, snorm[k]);
            rk[(r << 6) + p] = k;
        }
        __syncthreads();

        // ---- final pick (same r-order + tie rule)
        if (tid < TILEP) {
            float bd = 3.4e38f;
            int   bk = 1 << 30;
#pragma unroll
            for (int r = 0; r < 3; r++) {
                float d = rd[(r << 6) + tid];
                int   k = rk[(r << 6) + tid];
                if (d < bd || (d == bd && k < bk)) { bd = d; bk = k; }
            }
            loss_acc += bd;                       // + Σx² added globally
            sbk[tid] = bk;
            atomicAdd(&shist[bk], 1u);
            out[OFF_IDX + nb + tid] = (float)bk;
        }
        __syncthreads();

        // ---- vectorized writeout: thread (c, 4-point group) -> STG.128
        {
            const int c  = tid & 63;
            const int gg = tid >> 6;              // 0..7
            float* op = out + (size_t)b * CDIM * HWDIM + hwb;
#pragma unroll
            for (int it = 0; it < 2; it++) {
                int g  = gg + (it << 3);          // 0..15
                int p0 = g << 2;
                int k0 = sbk[p0], k1 = sbk[p0 + 1], k2 = sbk[p0 + 2], k3 = sbk[p0 + 3];
                float4 v;
                v.x = E[(k0 << 6) + c];
                v.y = E[(k1 << 6) + c];
                v.z = E[(k2 << 6) + c];
                v.w = E[(k3 << 6) + c];
                *reinterpret_cast<float4*>(op + (size_t)c * HWDIM + p0) = v;
            }
        }
    }

    // ---- block reductions -> globals
    float tot = loss_acc + xsq_acc;
#pragma unroll
    for (int off = 16; off; off >>= 1)
        tot += __shfl_xor_sync(0xFFFFFFFFu, tot, off);
    if (lane == 0) wsum[wid] = tot;
    __syncthreads();

    atomicAdd(&g_hist[tid], shist[tid]);
    if (tid == 0) {
        float bsum = 0.f;
#pragma unroll
        for (int i = 0; i < 16; i++) bsum += wsum[i];
        atomicAdd(&g_loss, bsum);
    }

    // ---- last-CTA fused finalize (graph-capturable, deterministic)
    __threadfence();
    if (tid == 0) s_rank = atomicAdd(&g_count, 1u);
    __syncthreads();
    if (s_rank == GRID - 1) {
        float pr  = (float)g_hist[tid] * (1.0f / (float)NTOT);
        float ent = pr * logf(pr + 1e-10f);
        float act = (w[tid] >= 0.01f) ? 1.f : 0.f;
#pragma unroll
        for (int off = 16; off; off >>= 1) {
            ent += __shfl_xor_sync(0xFFFFFFFFu, ent, off);
            act += __shfl_xor_sync(0xFFFFFFFFu, act, off);
        }
        if (lane == 0) { wsum[wid] = ent; sxf[wid] = act; }
        __syncthreads();
        if (tid == 0) {
            float esum = 0.f, asum = 0.f;
#pragma unroll
            for (int i = 0; i < 16; i++) { esum += wsum[i]; asum += sxf[i]; }
            out[OFF_LOSS] = g_loss * (1.0f / ((float)NTOT * (float)CDIM));
            out[OFF_PERP] = expf(-esum);
            out[OFF_ACT]  = asum;
        }
        __syncthreads();
        g_hist[tid] = 0u;                         // reset for next replay
        if (tid == 0) { g_loss = 0.f; g_count = 0u; }
    }
}

// ---------------------------------------------------------------------------
extern "C" void kernel_launch(void* const* d_in, const int* in_sizes, int n_in,
                              void* d_out, int out_size) {
    const float* x = (const float*)d_in[0];   // [16,64,64,64]
    const float* E = (const float*)d_in[1];   // [512,64]
    const float* w = (const float*)d_in[2];   // [512]
    float* out = (float*)d_out;

    cudaFuncSetAttribute(vq_main, cudaFuncAttributeMaxDynamicSharedMemorySize,
                         SMEM_BYTES);

    vq_main<<<GRID, TPB, SMEM_BYTES>>>(x, E, w, out);
}

// round 15
// speedup vs baseline: 1.0732x; 1.0732x over previous
#include <cuda_runtime.h>
#include <cuda_bf16.h>
#include <cstdint>

// Problem constants
#define NB      16
#define CDIM    64
#define HWDIM   4096
#define NTOT    65536
#define KCB     512
#define OUT_Q   4194304
#define OFF_LOSS (OUT_Q)
#define OFF_PERP (OUT_Q + 1)
#define OFF_ACT  (OUT_Q + 2)
#define OFF_IDX  (OUT_Q + 3)

#define TPB     512
#define GRID    148
#define TILEP   64
#define NTILES  (NTOT / TILEP)      // 1024 -> 6.92/CTA -> 0.988 balance

// smem rows padded to 72 halves (144B = 36 banks) -> ldmatrix conflict-free
#define ROWB    144
// ---- dynamic smem byte offsets ----
#define SO_BHI   0                  // E_hi bf16 [512][72h]  = 73728
#define SO_BLO   73728              // E_lo                  = 73728
#define SO_AHI   147456             // X_hi bf16 [64][72h]   =  9216
#define SO_ALO   156672             // X_lo                  =  9216
#define SO_XF    165888             // X fp32 [64][68]       = 17408
#define SO_SNORM 183296             // 512 f                 =  2048
#define SO_H     185344             // 512 f (= norm/2)      =  2048
#define SO_SD    187392             // float [64][8][2]      =  4096
#define SO_SI    191488             // int   [64][8][2]      =  4096
#define SO_HIST  195584             // 512 u32               =  2048
#define SO_SBK   197632             // 64 int                =   256
#define SO_WSUM  197888             // 16 f                  =    64
#define SO_RD    197952             // float [3][64]         =   768
#define SO_RK    198720             // int   [3][64]         =   768
#define SMEM_BYTES 199488

__device__ float        g_loss;
__device__ unsigned int g_hist[KCB];
__device__ unsigned int g_count;

// ---------------- family-portable tensor helpers (sm_80+ PTX only) --------
__device__ __forceinline__ void mma16816(float* d, const uint32_t* a,
                                         const uint32_t* b) {
    asm volatile(
        "mma.sync.aligned.m16n8k16.row.col.f32.bf16.bf16.f32 "
        "{%0,%1,%2,%3}, {%4,%5,%6,%7}, {%8,%9}, {%0,%1,%2,%3};"
        : "+f"(d[0]), "+f"(d[1]), "+f"(d[2]), "+f"(d[3])
        : "r"(a[0]), "r"(a[1]), "r"(a[2]), "r"(a[3]), "r"(b[0]), "r"(b[1]));
}
__device__ __forceinline__ void ldsm4(uint32_t* r, uint32_t addr) {
    asm volatile("ldmatrix.sync.aligned.m8n8.x4.shared.b16 {%0,%1,%2,%3}, [%4];"
                 : "=r"(r[0]), "=r"(r[1]), "=r"(r[2]), "=r"(r[3]) : "r"(addr));
}
__device__ __forceinline__ void pack_hilo(float f0, float f1,
                                          uint32_t& whi, uint32_t& wlo) {
    __nv_bfloat16 h0 = __float2bfloat16_rn(f0);
    __nv_bfloat16 h1 = __float2bfloat16_rn(f1);
    float r0 = f0 - __bfloat162float(h0);
    float r1 = f1 - __bfloat162float(h1);
    __nv_bfloat16 l0 = __float2bfloat16_rn(r0);
    __nv_bfloat16 l1 = __float2bfloat16_rn(r1);
    whi = (uint32_t)__bfloat16_as_ushort(h0) | ((uint32_t)__bfloat16_as_ushort(h1) << 16);
    wlo = (uint32_t)__bfloat16_as_ushort(l0) | ((uint32_t)__bfloat16_as_ushort(l1) << 16);
}
__device__ __forceinline__ void top2_upd(float m, int k,
                                         float& b1, float& b2, int& k1, int& k2) {
    if (m > b2) {
        if (m > b1) { b2 = b1; k2 = k1; b1 = m; k1 = k; }
        else        { b2 = m;  k2 = k; }
    }
}
__device__ __forceinline__ void top3_upd(float m, int k,
                                         float& b1, float& b2, float& b3,
                                         int& k1, int& k2, int& k3) {
    if (m > b3) {
        if (m > b2) {
            b3 = b2; k3 = k2;
            if (m > b1) { b2 = b1; k2 = k1; b1 = m; k1 = k; }
            else        { b2 = m;  k2 = k; }
        } else { b3 = m; k3 = k; }
    }
}
#define SHFL_MERGE2(off, t1, t2, k1, k2)                          \
    do {                                                          \
        float _o1 = __shfl_xor_sync(0xFFFFFFFFu, t1, off);        \
        float _o2 = __shfl_xor_sync(0xFFFFFFFFu, t2, off);        \
        int   _q1 = __shfl_xor_sync(0xFFFFFFFFu, k1, off);        \
        int   _q2 = __shfl_xor_sync(0xFFFFFFFFu, k2, off);        \
        top2_upd(_o1, _q1, t1, t2, k1, k2);                       \
        top2_upd(_o2, _q2, t1, t2, k1, k2);                       \
    } while (0)

// ---------------------------------------------------------------------------
extern __shared__ char sm[];

__global__ __launch_bounds__(TPB, 1)
void vq_main(const float* __restrict__ x,
             const float* __restrict__ E,
             const float* __restrict__ w,
             float* __restrict__ out) {
    float*        sxf   = (float*)(sm + SO_XF);
    float*        snorm = (float*)(sm + SO_SNORM);
    float*        hh    = (float*)(sm + SO_H);
    float*        sd    = (float*)(sm + SO_SD);
    int*          si    = (int*)(sm + SO_SI);
    unsigned int* shist = (unsigned int*)(sm + SO_HIST);
    int*          sbk   = (int*)(sm + SO_SBK);
    float*        wsum  = (float*)(sm + SO_WSUM);
    float*        rd    = (float*)(sm + SO_RD);
    int*          rk    = (int*)(sm + SO_RK);
    __shared__ unsigned int s_rank;

    const int tid  = threadIdx.x;
    const int wid  = tid >> 5;
    const int lane = tid & 31;

    // ---- one-time: codebook -> bf16 hi/lo (padded rows) + norms
    {
        const int k = tid;
        const float4* er = reinterpret_cast<const float4*>(E + (k << 6));
        char* bh = sm + SO_BHI + k * ROWB;
        char* bl = sm + SO_BLO + k * ROWB;
        float s = 0.f;
#pragma unroll
        for (int i = 0; i < 16; i++) {
            float4 v = er[i];
            s = fmaf(v.x, v.x, s); s = fmaf(v.y, v.y, s);
            s = fmaf(v.z, v.z, s); s = fmaf(v.w, v.w, s);
            uint32_t whi, wlo;
            pack_hilo(v.x, v.y, whi, wlo);
            *(uint32_t*)(bh + i * 8)     = whi;
            *(uint32_t*)(bl + i * 8)     = wlo;
            pack_hilo(v.z, v.w, whi, wlo);
            *(uint32_t*)(bh + i * 8 + 4) = whi;
            *(uint32_t*)(bl + i * 8 + 4) = wlo;
        }
        snorm[k] = s;
        hh[k]    = 0.5f * s;
        shist[k] = 0u;
    }
    __syncthreads();

    const int pw  = tid & 63;     // staging point
    const int cgi = tid >> 6;     // staging channel group (0..7)
    const int rg  = wid >> 3;     // row half: points rg*32 .. +31 (2 M-tiles)
    const int wq  = wid & 7;      // code eighth: codes wq*64 .. +63
    const int kbase = wq << 6;

    // ldmatrix lane addressing
    const uint32_t smu = (uint32_t)__cvta_generic_to_shared(sm);
    const int sel = lane >> 3;
    const uint32_t acol  = (uint32_t)((sel >> 1) << 4);
    const uint32_t arow0 = (uint32_t)(rg * 32 + (lane & 7) + ((sel & 1) << 3));
    const uint32_t aoff0 = arow0 * ROWB + acol;          // M-tile 0
    const uint32_t aoff1 = (arow0 + 16) * ROWB + acol;   // M-tile 1
    const uint32_t bln   = (uint32_t)((lane & 7) * ROWB + (lane >> 3) * 16);
    const uint32_t bhiB  = smu + SO_BHI + (uint32_t)kbase * ROWB + bln;
    const uint32_t bloB  = smu + SO_BLO + (uint32_t)kbase * ROWB + bln;

    float loss_acc = 0.f, xsq_acc = 0.f;

    for (int t = blockIdx.x; t < NTILES; t += GRID) {
        const int nb  = t << 6;
        const int b   = nb >> 12;
        const int hwb = nb & (HWDIM - 1);
        const float* xg = x + (size_t)b * CDIM * HWDIM + hwb;

        // ---- stage X tile: bf16 hi/lo (MMA A) + fp32 (rescore)
#pragma unroll
        for (int jj = 0; jj < 4; jj++) {
            int c0 = (cgi << 3) + (jj << 1);
            float v0 = xg[(size_t)c0 * HWDIM + pw];
            float v1 = xg[(size_t)(c0 + 1) * HWDIM + pw];
            xsq_acc = fmaf(v0, v0, xsq_acc);
            xsq_acc = fmaf(v1, v1, xsq_acc);
            uint32_t whi, wlo;
            pack_hilo(v0, v1, whi, wlo);
            *(uint32_t*)(sm + SO_AHI + pw * ROWB + c0 * 2) = whi;
            *(uint32_t*)(sm + SO_ALO + pw * ROWB + c0 * 2) = wlo;
            sxf[pw * 68 + c0]     = v0;
            sxf[pw * 68 + c0 + 1] = v1;
        }
        __syncthreads();

        // ---- A fragments: both M-tiles, hi+lo (persist across the nt loop)
        uint32_t ahi0[16], alo0[16], ahi1[16], alo1[16];
#pragma unroll
        for (int kt = 0; kt < 4; kt++) {
            ldsm4(ahi0 + 4 * kt, smu + SO_AHI + aoff0 + kt * 32);
            ldsm4(alo0 + 4 * kt, smu + SO_ALO + aoff0 + kt * 32);
            ldsm4(ahi1 + 4 * kt, smu + SO_AHI + aoff1 + kt * 32);
            ldsm4(alo1 + 4 * kt, smu + SO_ALO + aoff1 + kt * 32);
        }

        // ---- per-lane top-2 per point-row, held across the 8-nt code sweep
        //      slots: 0:(m0,r) 1:(m0,r+8) 2:(m1,r) 3:(m1,r+8)
        float t1_0 = -3.4e38f, t2_0 = -3.4e38f;
        float t1_1 = -3.4e38f, t2_1 = -3.4e38f;
        float t1_2 = -3.4e38f, t2_2 = -3.4e38f;
        float t1_3 = -3.4e38f, t2_3 = -3.4e38f;
        int k1_0 = 0, k2_0 = 0, k1_1 = 0, k2_1 = 0;
        int k1_2 = 0, k2_2 = 0, k1_3 = 0, k2_3 = 0;

#pragma unroll
        for (int nt = 0; nt < 8; nt++) {
            const uint32_t nbyt = (uint32_t)(nt * 8) * ROWB;
            uint32_t bh[8], bl[8];
            ldsm4(bh,     bhiB + nbyt);
            ldsm4(bh + 4, bhiB + nbyt + 64);
            ldsm4(bl,     bloB + nbyt);
            ldsm4(bl + 4, bloB + nbyt + 64);
            const int c0 = kbase + nt * 8 + 2 * (lane & 3);
            float2 hp = *(const float2*)(hh + c0);
            // M-tile 0: 3 independent 4-deep MMA chains
            {
                float a1[4] = {-hp.x, -hp.y, -hp.x, -hp.y};
                float a2[4] = {0.f, 0.f, 0.f, 0.f};
                float a3[4] = {0.f, 0.f, 0.f, 0.f};
#pragma unroll
                for (int kt = 0; kt < 4; kt++) {
                    mma16816(a1, ahi0 + 4 * kt, bh + 2 * kt);   // hi*hi
                    mma16816(a2, alo0 + 4 * kt, bh + 2 * kt);   // lo*hi
                    mma16816(a3, ahi0 + 4 * kt, bl + 2 * kt);   // hi*lo
                }
                top2_upd((a1[0] + a3[0]) + a2[0], c0,     t1_0, t2_0, k1_0, k2_0);
                top2_upd((a1[1] + a3[1]) + a2[1], c0 + 1, t1_0, t2_0, k1_0, k2_0);
                top2_upd((a1[2] + a3[2]) + a2[2], c0,     t1_1, t2_1, k1_1, k2_1);
                top2_upd((a1[3] + a3[3]) + a2[3], c0 + 1, t1_1, t2_1, k1_1, k2_1);
            }
            // M-tile 1
            {
                float a1[4] = {-hp.x, -hp.y, -hp.x, -hp.y};
                float a2[4] = {0.f, 0.f, 0.f, 0.f};
                float a3[4] = {0.f, 0.f, 0.f, 0.f};
#pragma unroll
                for (int kt = 0; kt < 4; kt++) {
                    mma16816(a1, ahi1 + 4 * kt, bh + 2 * kt);
                    mma16816(a2, alo1 + 4 * kt, bh + 2 * kt);
                    mma16816(a3, ahi1 + 4 * kt, bl + 2 * kt);
                }
                top2_upd((a1[0] + a3[0]) + a2[0], c0,     t1_2, t2_2, k1_2, k2_2);
                top2_upd((a1[1] + a3[1]) + a2[1], c0 + 1, t1_2, t2_2, k1_2, k2_2);
                top2_upd((a1[2] + a3[2]) + a2[2], c0,     t1_3, t2_3, k1_3, k2_3);
                top2_upd((a1[3] + a3[3]) + a2[3], c0 + 1, t1_3, t2_3, k1_3, k2_3);
            }
        }

        // ---- merge across the 4 lanes sharing each row (bfly 1,2), ONCE
#pragma unroll
        for (int off = 1; off <= 2; off <<= 1) {
            SHFL_MERGE2(off, t1_0, t2_0, k1_0, k2_0);
            SHFL_MERGE2(off, t1_1, t2_1, k1_1, k2_1);
            SHFL_MERGE2(off, t1_2, t2_2, k1_2, k2_2);
            SHFL_MERGE2(off, t1_3, t2_3, k1_3, k2_3);
        }
        if ((lane & 3) == 0) {
            const int r  = lane >> 2;             // 0..7
            const int pa = rg * 32 + r;           // m0, row r
            const int pb = pa + 8;                // m0, row r+8
            const int pc = pa + 16;               // m1, row r
            const int pd = pa + 24;               // m1, row r+8
            int ba = (pa * 8 + wq) * 2, bb = (pb * 8 + wq) * 2;
            int bc = (pc * 8 + wq) * 2, bd = (pd * 8 + wq) * 2;
            sd[ba] = t1_0; sd[ba + 1] = t2_0; si[ba] = k1_0; si[ba + 1] = k2_0;
            sd[bb] = t1_1; sd[bb + 1] = t2_1; si[bb] = k1_1; si[bb + 1] = k2_1;
            sd[bc] = t1_2; sd[bc + 1] = t2_2; si[bc] = k1_2; si[bc + 1] = k2_2;
            sd[bd] = t1_3; sd[bd + 1] = t2_3; si[bd] = k1_3; si[bd + 1] = k2_3;
        }
        __syncthreads();

        // ---- distributed exact rescore: thread (p, r), r = tid>>6 < 3.
        //      Redundant deterministic top-3 over 16 candidates; EXACT fp32
        //      distance in R1 formula/order.
        if (tid < 192) {
            const int p = tid & 63;
            const int r = tid >> 6;
            float m1 = -3.4e38f, m2 = -3.4e38f, m3 = -3.4e38f;
            int   i1 = 0, i2 = 0, i3 = 0;
#pragma unroll
            for (int ww = 0; ww < 8; ww++) {
                int bidx = (p * 8 + ww) * 2;
                top3_upd(sd[bidx],     si[bidx],     m1, m2, m3, i1, i2, i3);
                top3_upd(sd[bidx + 1], si[bidx + 1], m1, m2, m3, i1, i2, i3);
            }
            const int k = (r == 0) ? i1 : (r == 1) ? i2 : i3;
            const float4* xr4 = reinterpret_cast<const float4*>(sxf + p * 68);
            const float4* er  = reinterpret_cast<const float4*>(E + (k << 6));
            float q0 = 0.f, q1 = 0.f, q2 = 0.f, q3 = 0.f;
#pragma unroll
            for (int i = 0; i < 16; i++) {
                float4 xv = xr4[i];
                float4 ev = er[i];
                q0 = fmaf(xv.x, ev.x, q0);
                q1 = fmaf(xv.y, ev.y, q1);
                q2 = fmaf(xv.z, ev.z, q2);
                q3 = fmaf(xv.w, ev.w, q3);
            }
            float dot = (q0 + q1) + (q2 + q3);
            rd[(r << 6) + p] = fmaf(-2.f, dot, snorm[k]);
            rk[(r << 6) + p] = k;
        }
        __syncthreads();

        // ---- final pick (same r-order + tie rule)
        if (tid < TILEP) {
            float bd = 3.4e38f;
            int   bk = 1 << 30;
#pragma unroll
            for (int r = 0; r < 3; r++) {
                float d = rd[(r << 6) + tid];
                int   k = rk[(r << 6) + tid];
                if (d < bd || (d == bd && k < bk)) { bd = d; bk = k; }
            }
            loss_acc += bd;                       // + Σx² added globally
            sbk[tid] = bk;
            atomicAdd(&shist[bk], 1u);
            out[OFF_IDX + nb + tid] = (float)bk;
        }
        __syncthreads();

        // ---- vectorized writeout: thread (c, 4-point group) -> STG.128
        {
            const int c  = tid & 63;
            const int gg = tid >> 6;              // 0..7
            float* op = out + (size_t)b * CDIM * HWDIM + hwb;
#pragma unroll
            for (int it = 0; it < 2; it++) {
                int g  = gg + (it << 3);          // 0..15
                int p0 = g << 2;
                int k0 = sbk[p0], k1 = sbk[p0 + 1], k2 = sbk[p0 + 2], k3 = sbk[p0 + 3];
                float4 v;
                v.x = E[(k0 << 6) + c];
                v.y = E[(k1 << 6) + c];
                v.z = E[(k2 << 6) + c];
                v.w = E[(k3 << 6) + c];
                *reinterpret_cast<float4*>(op + (size_t)c * HWDIM + p0) = v;
            }
        }
    }

    // ---- block reductions -> globals
    float tot = loss_acc + xsq_acc;
#pragma unroll
    for (int off = 16; off; off >>= 1)
        tot += __shfl_xor_sync(0xFFFFFFFFu, tot, off);
    if (lane == 0) wsum[wid] = tot;
    __syncthreads();

    atomicAdd(&g_hist[tid], shist[tid]);
    if (tid == 0) {
        float bsum = 0.f;
#pragma unroll
        for (int i = 0; i < 16; i++) bsum += wsum[i];
        atomicAdd(&g_loss, bsum);
    }

    // ---- last-CTA fused finalize (graph-capturable, deterministic)
    __threadfence();
    if (tid == 0) s_rank = atomicAdd(&g_count, 1u);
    __syncthreads();
    if (s_rank == GRID - 1) {
        float pr  = (float)g_hist[tid] * (1.0f / (float)NTOT);
        float ent = pr * logf(pr + 1e-10f);
        float act = (w[tid] >= 0.01f) ? 1.f : 0.f;
#pragma unroll
        for (int off = 16; off; off >>= 1) {
            ent += __shfl_xor_sync(0xFFFFFFFFu, ent, off);
            act += __shfl_xor_sync(0xFFFFFFFFu, act, off);
        }
        if (lane == 0) { wsum[wid] = ent; sxf[wid] = act; }
        __syncthreads();
        if (tid == 0) {
            float esum = 0.f, asum = 0.f;
#pragma unroll
            for (int i = 0; i < 16; i++) { esum += wsum[i]; asum += sxf[i]; }
            out[OFF_LOSS] = g_loss * (1.0f / ((float)NTOT * (float)CDIM));
            out[OFF_PERP] = expf(-esum);
            out[OFF_ACT]  = asum;
        }
        __syncthreads();
        g_hist[tid] = 0u;                         // reset for next replay
        if (tid == 0) { g_loss = 0.f; g_count = 0u; }
    }
}

// ---------------------------------------------------------------------------
extern "C" void kernel_launch(void* const* d_in, const int* in_sizes, int n_in,
                              void* d_out, int out_size) {
    const float* x = (const float*)d_in[0];   // [16,64,64,64]
    const float* E = (const float*)d_in[1];   // [512,64]
    const float* w = (const float*)d_in[2];   // [512]
    float* out = (float*)d_out;

    cudaFuncSetAttribute(vq_main, cudaFuncAttributeMaxDynamicSharedMemorySize,
                         SMEM_BYTES);

    vq_main<<<GRID, TPB, SMEM_BYTES>>>(x, E, w, out);
}

// round 16
// speedup vs baseline: 1.2309x; 1.1470x over previous
#include <cuda_runtime.h>
#include <cuda_fp16.h>
#include <cstdint>

// Problem constants
#define NB      16
#define CDIM    64
#define HWDIM   4096
#define NTOT    65536
#define KCB     512
#define OUT_Q   4194304
#define OFF_LOSS (OUT_Q)
#define OFF_PERP (OUT_Q + 1)
#define OFF_ACT  (OUT_Q + 2)
#define OFF_IDX  (OUT_Q + 3)

#define TPB     1024                // 32 warps -> occ 50%
#define GRID    148
#define TILEP   64
#define NTILES  (NTOT / TILEP)      // 1024 -> 6.92/CTA -> 0.988 balance

// smem rows padded to 72 halves (144B = 36 banks) -> ldmatrix conflict-free
#define ROWB    144
// ---- dynamic smem byte offsets ----
#define SO_EH    0                  // E_hi fp16 [512][72h]  = 73728
#define SO_EL    73728              // E_lo fp16             = 73728
#define SO_XH    147456             // X_hi fp16 [64][72h]   =  9216
#define SO_XF    156672             // X fp32 [64][68]       = 17408
#define SO_SNORM 174080             // 512 f                 =  2048
#define SO_H     176128             // 512 f (= norm/2)      =  2048
#define SO_SD    178176             // float [64][8][2]      =  4096
#define SO_SI    182272             // int   [64][8][2]      =  4096
#define SO_HIST  186368             // 512 u32               =  2048
#define SO_SBK   188416             // 64 int                =   256
#define SO_WSUM  188672             // 32 f                  =   128
#define SO_RD    188800             // float [3][64]         =   768
#define SO_RK    189568             // int   [3][64]         =   768
#define SMEM_BYTES 190336

__device__ float        g_loss;
__device__ unsigned int g_hist[KCB];
__device__ unsigned int g_count;

// ---------------- family-portable tensor helpers (sm_80+ PTX only) --------
__device__ __forceinline__ void mma_f16(float* d, const uint32_t* a,
                                        const uint32_t* b) {
    asm volatile(
        "mma.sync.aligned.m16n8k16.row.col.f32.f16.f16.f32 "
        "{%0,%1,%2,%3}, {%4,%5,%6,%7}, {%8,%9}, {%0,%1,%2,%3};"
        : "+f"(d[0]), "+f"(d[1]), "+f"(d[2]), "+f"(d[3])
        : "r"(a[0]), "r"(a[1]), "r"(a[2]), "r"(a[3]), "r"(b[0]), "r"(b[1]));
}
__device__ __forceinline__ void ldsm4(uint32_t* r, uint32_t addr) {
    asm volatile("ldmatrix.sync.aligned.m8n8.x4.shared.b16 {%0,%1,%2,%3}, [%4];"
                 : "=r"(r[0]), "=r"(r[1]), "=r"(r[2]), "=r"(r[3]) : "r"(addr));
}
__device__ __forceinline__ uint32_t pack_h2(float f0, float f1) {
    __half h0 = __float2half_rn(f0);
    __half h1 = __float2half_rn(f1);
    return (uint32_t)__half_as_ushort(h0) | ((uint32_t)__half_as_ushort(h1) << 16);
}
__device__ __forceinline__ void pack_hilo_f16(float f0, float f1,
                                              uint32_t& whi, uint32_t& wlo) {
    __half h0 = __float2half_rn(f0);
    __half h1 = __float2half_rn(f1);
    float r0 = f0 - __half2float(h0);
    float r1 = f1 - __half2float(h1);
    __half l0 = __float2half_rn(r0);
    __half l1 = __float2half_rn(r1);
    whi = (uint32_t)__half_as_ushort(h0) | ((uint32_t)__half_as_ushort(h1) << 16);
    wlo = (uint32_t)__half_as_ushort(l0) | ((uint32_t)__half_as_ushort(l1) << 16);
}
__device__ __forceinline__ void top2_upd(float m, int k,
                                         float& b1, float& b2, int& k1, int& k2) {
    if (m > b2) {
        if (m > b1) { b2 = b1; k2 = k1; b1 = m; k1 = k; }
        else        { b2 = m;  k2 = k; }
    }
}
__device__ __forceinline__ void top3_upd(float m, int k,
                                         float& b1, float& b2, float& b3,
                                         int& k1, int& k2, int& k3) {
    if (m > b3) {
        if (m > b2) {
            b3 = b2; k3 = k2;
            if (m > b1) { b2 = b1; k2 = k1; b1 = m; k1 = k; }
            else        { b2 = m;  k2 = k; }
        } else { b3 = m; k3 = k; }
    }
}
#define SHFL_MERGE2(off, t1, t2, k1, k2)                          \
    do {                                                          \
        float _o1 = __shfl_xor_sync(0xFFFFFFFFu, t1, off);        \
        float _o2 = __shfl_xor_sync(0xFFFFFFFFu, t2, off);        \
        int   _q1 = __shfl_xor_sync(0xFFFFFFFFu, k1, off);        \
        int   _q2 = __shfl_xor_sync(0xFFFFFFFFu, k2, off);        \
        top2_upd(_o1, _q1, t1, t2, k1, k2);                       \
        top2_upd(_o2, _q2, t1, t2, k1, k2);                       \
    } while (0)

// ---------------------------------------------------------------------------
extern __shared__ char sm[];

__global__ __launch_bounds__(TPB, 1)
void vq_main(const float* __restrict__ x,
             const float* __restrict__ E,
             const float* __restrict__ w,
             float* __restrict__ out) {
    float*        sxf   = (float*)(sm + SO_XF);
    float*        snorm = (float*)(sm + SO_SNORM);
    float*        hh    = (float*)(sm + SO_H);
    float*        sd    = (float*)(sm + SO_SD);
    int*          si    = (int*)(sm + SO_SI);
    unsigned int* shist = (unsigned int*)(sm + SO_HIST);
    int*          sbk   = (int*)(sm + SO_SBK);
    float*        wsum  = (float*)(sm + SO_WSUM);
    float*        rd    = (float*)(sm + SO_RD);
    int*          rk    = (int*)(sm + SO_RK);
    __shared__ unsigned int s_rank;

    const int tid  = threadIdx.x;
    const int wid  = tid >> 5;
    const int lane = tid & 31;

    // ---- one-time: codebook -> fp16 hi/lo (padded rows) + norms
    if (tid < KCB) {
        const int k = tid;
        const float4* er = reinterpret_cast<const float4*>(E + (k << 6));
        char* bh = sm + SO_EH + k * ROWB;
        char* bl = sm + SO_EL + k * ROWB;
        float s = 0.f;
#pragma unroll
        for (int i = 0; i < 16; i++) {
            float4 v = er[i];
            s = fmaf(v.x, v.x, s); s = fmaf(v.y, v.y, s);
            s = fmaf(v.z, v.z, s); s = fmaf(v.w, v.w, s);
            uint32_t whi, wlo;
            pack_hilo_f16(v.x, v.y, whi, wlo);
            *(uint32_t*)(bh + i * 8)     = whi;
            *(uint32_t*)(bl + i * 8)     = wlo;
            pack_hilo_f16(v.z, v.w, whi, wlo);
            *(uint32_t*)(bh + i * 8 + 4) = whi;
            *(uint32_t*)(bl + i * 8 + 4) = wlo;
        }
        snorm[k] = s;
        hh[k]    = 0.5f * s;
        shist[k] = 0u;
    }
    __syncthreads();

    const int pw  = tid & 63;     // staging point
    const int cgi = tid >> 6;     // staging channel group (0..15)
    const int rg  = wid >> 3;     // row group: points rg*16 .. +15
    const int wq  = wid & 7;      // code eighth: codes wq*64 .. +63
    const int kbase = wq << 6;

    // ldmatrix lane addressing
    const uint32_t smu = (uint32_t)__cvta_generic_to_shared(sm);
    const int sel = lane >> 3;
    const uint32_t aoff =
        (uint32_t)(rg * 16 + (lane & 7) + ((sel & 1) << 3)) * ROWB
        + (uint32_t)((sel >> 1) << 4);
    const uint32_t ahiA = smu + SO_XH + aoff;
    const uint32_t bln  = (uint32_t)((lane & 7) * ROWB + (lane >> 3) * 16);
    const uint32_t bhiB = smu + SO_EH + (uint32_t)kbase * ROWB + bln;
    const uint32_t bloB = smu + SO_EL + (uint32_t)kbase * ROWB + bln;

    float loss_acc = 0.f, xsq_acc = 0.f;

    for (int t = blockIdx.x; t < NTILES; t += GRID) {
        const int nb  = t << 6;
        const int b   = nb >> 12;
        const int hwb = nb & (HWDIM - 1);
        const float* xg = x + (size_t)b * CDIM * HWDIM + hwb;

        // ---- stage X tile: fp16 hi (MMA A) + fp32 (rescore); 4 ch/thread
#pragma unroll
        for (int jj = 0; jj < 2; jj++) {
            int c0 = (cgi << 2) + (jj << 1);
            float v0 = xg[(size_t)c0 * HWDIM + pw];
            float v1 = xg[(size_t)(c0 + 1) * HWDIM + pw];
            xsq_acc = fmaf(v0, v0, xsq_acc);
            xsq_acc = fmaf(v1, v1, xsq_acc);
            *(uint32_t*)(sm + SO_XH + pw * ROWB + c0 * 2) = pack_h2(v0, v1);
            sxf[pw * 68 + c0]     = v0;
            sxf[pw * 68 + c0 + 1] = v1;
        }
        __syncthreads();

        // ---- A fragments: hi only (persist across the nt loop)
        uint32_t ahi[16];
#pragma unroll
        for (int kt = 0; kt < 4; kt++)
            ldsm4(ahi + 4 * kt, ahiA + kt * 32);

        // ---- per-lane top-2 per point-row, held across the 8-nt code sweep
        float t1_0 = -3.4e38f, t2_0 = -3.4e38f;   // row rg*16 + (lane>>2)
        float t1_1 = -3.4e38f, t2_1 = -3.4e38f;   // row +8
        int k1_0 = 0, k2_0 = 0, k1_1 = 0, k2_1 = 0;

#pragma unroll
        for (int nt = 0; nt < 8; nt++) {
            const uint32_t nbyt = (uint32_t)(nt * 8) * ROWB;
            uint32_t bh[8], bl[8];
            ldsm4(bh,     bhiB + nbyt);
            ldsm4(bh + 4, bhiB + nbyt + 64);
            ldsm4(bl,     bloB + nbyt);
            ldsm4(bl + 4, bloB + nbyt + 64);
            const int c0 = kbase + nt * 8 + 2 * (lane & 3);
            float2 hp = *(const float2*)(hh + c0);
            float a1[4] = {-hp.x, -hp.y, -hp.x, -hp.y};   // h folded in
            float a2[4] = {0.f, 0.f, 0.f, 0.f};
#pragma unroll
            for (int kt = 0; kt < 4; kt++) {
                mma_f16(a1, ahi + 4 * kt, bh + 2 * kt);   // xh * eh
                mma_f16(a2, ahi + 4 * kt, bl + 2 * kt);   // xh * el
            }
            top2_upd(a1[0] + a2[0], c0,     t1_0, t2_0, k1_0, k2_0);
            top2_upd(a1[1] + a2[1], c0 + 1, t1_0, t2_0, k1_0, k2_0);
            top2_upd(a1[2] + a2[2], c0,     t1_1, t2_1, k1_1, k2_1);
            top2_upd(a1[3] + a2[3], c0 + 1, t1_1, t2_1, k1_1, k2_1);
        }

        // ---- merge across the 4 lanes sharing each row (bfly 1,2), ONCE
#pragma unroll
        for (int off = 1; off <= 2; off <<= 1) {
            SHFL_MERGE2(off, t1_0, t2_0, k1_0, k2_0);
            SHFL_MERGE2(off, t1_1, t2_1, k1_1, k2_1);
        }
        if ((lane & 3) == 0) {
            const int r  = lane >> 2;             // 0..7
            const int pa = rg * 16 + r;
            const int pb = pa + 8;
            int ba = (pa * 8 + wq) * 2;
            int bb = (pb * 8 + wq) * 2;
            sd[ba] = t1_0; sd[ba + 1] = t2_0; si[ba] = k1_0; si[ba + 1] = k2_0;
            sd[bb] = t1_1; sd[bb + 1] = t2_1; si[bb] = k1_1; si[bb + 1] = k2_1;
        }
        __syncthreads();

        // ---- distributed exact rescore: thread (p, r), r = tid>>6 < 3.
        //      Redundant deterministic top-3 over 16 candidates; EXACT fp32
        //      distance in R1 formula/order.
        if (tid < 192) {
            const int p = tid & 63;
            const int r = tid >> 6;
            float m1 = -3.4e38f, m2 = -3.4e38f, m3 = -3.4e38f;
            int   i1 = 0, i2 = 0, i3 = 0;
#pragma unroll
            for (int ww = 0; ww < 8; ww++) {
                int bidx = (p * 8 + ww) * 2;
                top3_upd(sd[bidx],     si[bidx],     m1, m2, m3, i1, i2, i3);
                top3_upd(sd[bidx + 1], si[bidx + 1], m1, m2, m3, i1, i2, i3);
            }
            const int k = (r == 0) ? i1 : (r == 1) ? i2 : i3;
            const float4* xr4 = reinterpret_cast<const float4*>(sxf + p * 68);
            const float4* er  = reinterpret_cast<const float4*>(E + (k << 6));
            float q0 = 0.f, q1 = 0.f, q2 = 0.f, q3 = 0.f;
#pragma unroll
            for (int i = 0; i < 16; i++) {
                float4 xv = xr4[i];
                float4 ev = er[i];
                q0 = fmaf(xv.x, ev.x, q0);
                q1 = fmaf(xv.y, ev.y, q1);
                q2 = fmaf(xv.z, ev.z, q2);
                q3 = fmaf(xv.w, ev.w, q3);
            }
            float dot = (q0 + q1) + (q2 + q3);
            rd[(r << 6) + p] = fmaf(-2.f, dot, snorm[k]);
            rk[(r << 6) + p] = k;
        }
        __syncthreads();

        // ---- final pick (same r-order + tie rule)
        if (tid < TILEP) {
            float bd = 3.4e38f;
            int   bk = 1 << 30;
#pragma unroll
            for (int r = 0; r < 3; r++) {
                float d = rd[(r << 6) + tid];
                int   k = rk[(r << 6) + tid];
                if (d < bd || (d == bd && k < bk)) { bd = d; bk = k; }
            }
            loss_acc += bd;                       // + Σx² added globally
            sbk[tid] = bk;
            atomicAdd(&shist[bk], 1u);
            out[OFF_IDX + nb + tid] = (float)bk;
        }
        __syncthreads();

        // ---- vectorized writeout: thread (c, 4-point group) -> STG.128
        {
            const int c = tid & 63;
            const int g = tid >> 6;               // 0..15
            float* op = out + (size_t)b * CDIM * HWDIM + hwb;
            int p0 = g << 2;
            int k0 = sbk[p0], k1 = sbk[p0 + 1], k2 = sbk[p0 + 2], k3 = sbk[p0 + 3];
            float4 v;
            v.x = E[(k0 << 6) + c];
            v.y = E[(k1 << 6) + c];
            v.z = E[(k2 << 6) + c];
            v.w = E[(k3 << 6) + c];
            *reinterpret_cast<float4*>(op + (size_t)c * HWDIM + p0) = v;
        }
        __syncthreads();
    }

    // ---- block reductions -> globals
    float tot = loss_acc + xsq_acc;
#pragma unroll
    for (int off = 16; off; off >>= 1)
        tot += __shfl_xor_sync(0xFFFFFFFFu, tot, off);
    if (lane == 0) wsum[wid] = tot;
    __syncthreads();

    if (tid < KCB) atomicAdd(&g_hist[tid], shist[tid]);
    if (tid == 0) {
        float bsum = 0.f;
#pragma unroll
        for (int i = 0; i < 32; i++) bsum += wsum[i];
        atomicAdd(&g_loss, bsum);
    }

    // ---- last-CTA fused finalize (graph-capturable, deterministic)
    __threadfence();
    if (tid == 0) s_rank = atomicAdd(&g_count, 1u);
    __syncthreads();
    if (s_rank == GRID - 1) {
        float ent = 0.f, act = 0.f;
        if (tid < KCB) {
            float pr = (float)g_hist[tid] * (1.0f / (float)NTOT);
            ent = pr * logf(pr + 1e-10f);
            act = (w[tid] >= 0.01f) ? 1.f : 0.f;
        }
#pragma unroll
        for (int off = 16; off; off >>= 1) {
            ent += __shfl_xor_sync(0xFFFFFFFFu, ent, off);
            act += __shfl_xor_sync(0xFFFFFFFFu, act, off);
        }
        if (lane == 0) { wsum[wid] = ent; sxf[wid] = act; }
        __syncthreads();
        if (tid == 0) {
            float esum = 0.f, asum = 0.f;
#pragma unroll
            for (int i = 0; i < 16; i++) { esum += wsum[i]; asum += sxf[i]; }
            out[OFF_LOSS] = g_loss * (1.0f / ((float)NTOT * (float)CDIM));
            out[OFF_PERP] = expf(-esum);
            out[OFF_ACT]  = asum;
        }
        __syncthreads();
        if (tid < KCB) g_hist[tid] = 0u;          // reset for next replay
        if (tid == 0) { g_loss = 0.f; g_count = 0u; }
    }
}

// ---------------------------------------------------------------------------
extern "C" void kernel_launch(void* const* d_in, const int* in_sizes, int n_in,
                              void* d_out, int out_size) {
    const float* x = (const float*)d_in[0];   // [16,64,64,64]
    const float* E = (const float*)d_in[1];   // [512,64]
    const float* w = (const float*)d_in[2];   // [512]
    float* out = (float*)d_out;

    cudaFuncSetAttribute(vq_main, cudaFuncAttributeMaxDynamicSharedMemorySize,
                         SMEM_BYTES);

    vq_main<<<GRID, TPB, SMEM_BYTES>>>(x, E, w, out);
}